// round 7
// baseline (speedup 1.0000x reference)
#include <cuda_runtime.h>

// ---------------------------------------------------------------------------
// R7: Fused 2-layer LSTM (H=4, I=2, T=50) + readout, 4 elements/thread
//     (2 element-PAIRS), quad of 4 lanes per 4 elements.
// R4/R5/R6 all pinned at ~212us / issue ~50% regardless of occupancy, ILP,
// or MUFU count -> hypothesis: per-warp var-lat scoreboard (6 wbar slots)
// serialization on 60 var-lat ops/warp-step (32 shfl + 28 MUFU).
// This round halves var-lat count:
//   - h of each element pair packed f16x2 -> ONE shfl moves both elements
//     (shfl 32 -> 16 per warp-step); unpack via fixed-lat cvt on idle alu pipe
//   - ALL activations in tanh.approx.f16x2 across the element pair
//     (MUFU 28 -> 20 per warp-step); c-update packed f32x2
//   - gate MACs unchanged: packed fma.rn.f32x2 over gate-pairs (i,f),(g,o)
// ---------------------------------------------------------------------------

#define T_STEPS 50
typedef unsigned long long ull;
typedef unsigned int u32;

__device__ __forceinline__ ull pk2(float lo, float hi) {
    ull r; asm("mov.b64 %0, {%1, %2};" : "=l"(r) : "f"(lo), "f"(hi)); return r;
}
__device__ __forceinline__ void upk2(ull v, float& lo, float& hi) {
    asm("mov.b64 {%0, %1}, %2;" : "=f"(lo), "=f"(hi) : "l"(v));
}
__device__ __forceinline__ ull ffma2(ull a, ull b, ull c) {
    ull d; asm("fma.rn.f32x2 %0, %1, %2, %3;" : "=l"(d) : "l"(a), "l"(b), "l"(c));
    return d;
}
__device__ __forceinline__ ull mul2(ull a, ull b) {
    ull d; asm("mul.rn.f32x2 %0, %1, %2;" : "=l"(d) : "l"(a), "l"(b)); return d;
}
__device__ __forceinline__ float ex2f(float x) {
    float r; asm("ex2.approx.f32 %0, %1;" : "=f"(r) : "f"(x)); return r;
}
__device__ __forceinline__ float rcpf(float x) {
    float r; asm("rcp.approx.f32 %0, %1;" : "=f"(r) : "f"(x)); return r;
}

// ---- f16x2 element-pair helpers (lo half = even element, hi half = odd) ----
__device__ __forceinline__ u32 h2pack(float lo, float hi) {
    u32 p;  // cvt.rn.f16x2.f32 d, A, B: A -> upper half, B -> lower half
    asm("cvt.rn.f16x2.f32 %0, %1, %2;" : "=r"(p) : "f"(hi), "f"(lo));
    return p;
}
__device__ __forceinline__ void h2unpack(u32 p, float& lo, float& hi) {
    asm("{\n\t.reg .b16 l, h;\n\tmov.b32 {l, h}, %2;\n\t"
        "cvt.f32.f16 %0, l;\n\tcvt.f32.f16 %1, h;\n\t}"
        : "=f"(lo), "=f"(hi) : "r"(p));
}
__device__ __forceinline__ u32 h2tanh(u32 p) {
    u32 r; asm("tanh.approx.f16x2 %0, %1;" : "=r"(r) : "r"(p)); return r;
}
// sigmoid of prescaled pre-act (x0.5 folded into weights): 0.5*tanh(y)+0.5
__device__ __forceinline__ u32 h2sig(u32 p) {
    u32 r;
    asm("{\n\ttanh.approx.f16x2 %0, %1;\n\t"
        "fma.rn.f16x2 %0, %0, %2, %2;\n\t}"
        : "=r"(r) : "r"(p), "r"(0x38003800u));
    return r;
}
__device__ __forceinline__ u32 hmul2(u32 a, u32 b) {
    u32 d; asm("mul.rn.f16x2 %0, %1, %2;" : "=r"(d) : "r"(a), "r"(b)); return d;
}
// f16x2 -> f32x2 (fixed-lat cvts on alu pipe)
__device__ __forceinline__ ull h2w(u32 p) {
    float lo, hi; h2unpack(p, lo, hi); return pk2(lo, hi);
}

// Paired LSTM pointwise block: inputs a0e*=(yi,yf), a1e*=(yg,yo) per element,
// c2 = packed f32x2 cell state for the pair. Returns packed f16x2 (h_e0, h_e1).
__device__ __forceinline__ u32 act_pair(ull a0e0, ull a0e1, ull a1e0, ull a1e1,
                                        ull& c2)
{
    float yi0, yf0, yi1, yf1, yg0, yo0, yg1, yo1;
    upk2(a0e0, yi0, yf0);  upk2(a0e1, yi1, yf1);
    upk2(a1e0, yg0, yo0);  upk2(a1e1, yg1, yo1);
    u32 si = h2sig(h2pack(yi0, yi1));
    u32 sf = h2sig(h2pack(yf0, yf1));
    u32 so = h2sig(h2pack(yo0, yo1));
    u32 tg = h2tanh(h2pack(yg0, yg1));
    c2 = ffma2(h2w(sf), c2, mul2(h2w(si), h2w(tg)));
    float cl, ch; upk2(c2, cl, ch);
    u32 tc = h2tanh(h2pack(cl, ch));
    return hmul2(so, tc);
}

#define NE 4  // elements per thread = 2 pairs

__global__ __launch_bounds__(128, 3) void lstm_fused4p(
    const float* __restrict__ x,     // [B, T, 2]
    const float* __restrict__ Wih0,  // [16, 2]
    const float* __restrict__ Whh0,  // [16, 4]
    const float* __restrict__ bih0,
    const float* __restrict__ bhh0,
    const float* __restrict__ Wih1,  // [16, 4]
    const float* __restrict__ Whh1,  // [16, 4]
    const float* __restrict__ bih1,
    const float* __restrict__ bhh1,
    const float* __restrict__ Wout,  // [1, 200], col = t*4 + u
    const float* __restrict__ bout,
    float* __restrict__ out,
    int B)
{
    int g = blockIdx.x * 128 + threadIdx.x;
    int q = g >> 2;            // quad owns elements 4q .. 4q+3
    int u = g & 3;             // hidden unit owned by this lane
    int eA = NE * q;
    if (eA >= B) return;
    int base = (threadIdx.x & 31) & ~3;

    // Gate rows for unit u: i=u, f=4+u, g=8+u, o=12+u.
    // Chain 0 = (i,f) scales (.5,.5); chain 1 = (g,o) scales (1,.5).
    const int   rlo[2] = { u,      8 + u };
    const int   rhi[2] = { 4 + u, 12 + u };
    const float slo[2] = { 0.5f, 1.0f };
    const float shi[2] = { 0.5f, 0.5f };

    ull wi0[2][2], wh0[2][4], b0[2];
    ull wi1[2][4], wh1[2][4], b1[2];
#pragma unroll
    for (int p = 0; p < 2; p++) {
        int lo = rlo[p], hi = rhi[p];
        float sl = slo[p], sh = shi[p];
#pragma unroll
        for (int k = 0; k < 2; k++)
            wi0[p][k] = pk2(sl * __ldg(&Wih0[lo * 2 + k]), sh * __ldg(&Wih0[hi * 2 + k]));
#pragma unroll
        for (int k = 0; k < 4; k++) {
            wh0[p][k] = pk2(sl * __ldg(&Whh0[lo * 4 + k]), sh * __ldg(&Whh0[hi * 4 + k]));
            wi1[p][k] = pk2(sl * __ldg(&Wih1[lo * 4 + k]), sh * __ldg(&Wih1[hi * 4 + k]));
            wh1[p][k] = pk2(sl * __ldg(&Whh1[lo * 4 + k]), sh * __ldg(&Whh1[hi * 4 + k]));
        }
        b0[p] = pk2(sl * (__ldg(&bih0[lo]) + __ldg(&bhh0[lo])),
                    sh * (__ldg(&bih0[hi]) + __ldg(&bhh0[hi])));
        b1[p] = pk2(sl * (__ldg(&bih1[lo]) + __ldg(&bhh1[lo])),
                    sh * (__ldg(&bih1[hi]) + __ldg(&bhh1[hi])));
    }

    // State: packed f32x2 cell per pair per layer; broadcast h as f16x2.
    ull c20[2] = {0ull, 0ull}, c21[2] = {0ull, 0ull};
    u32 hb0[2][4] = {{0u,0u,0u,0u},{0u,0u,0u,0u}};   // layer0 h, all units
    u32 hb1[2][4] = {{0u,0u,0u,0u},{0u,0u,0u,0u}};   // layer1 h, all units
    float z[NE] = {0.f, 0.f, 0.f, 0.f};

    const float4* xb = reinterpret_cast<const float4*>(x + (size_t)eA * (T_STEPS * 2));

#pragma unroll 1
    for (int tt = 0; tt < T_STEPS / 2; ++tt) {
        float4 xv[NE];
#pragma unroll
        for (int e = 0; e < NE; e++) xv[e] = __ldg(&xb[tt + e * (T_STEPS / 2)]);
        float wo  = __ldg(&Wout[(2 * tt) * 4 + u]);
        float wo2 = __ldg(&Wout[(2 * tt + 1) * 4 + u]);

#pragma unroll
        for (int s = 0; s < 2; s++) {
            // ================= layer 0: MACs for all 4 elements =============
            ull a0[NE], a1[NE];
#pragma unroll
            for (int P = 0; P < 2; P++) {
                float hL[4], hH[4];
#pragma unroll
                for (int k = 0; k < 4; k++) h2unpack(hb0[P][k], hL[k], hH[k]);
#pragma unroll
                for (int j = 0; j < 2; j++) {
                    int e = 2 * P + j;
                    float x0 = s ? xv[e].z : xv[e].x;
                    float x1 = s ? xv[e].w : xv[e].y;
                    ull dh0 = j ? pk2(hH[0], hH[0]) : pk2(hL[0], hL[0]);
                    ull dh1 = j ? pk2(hH[1], hH[1]) : pk2(hL[1], hL[1]);
                    ull dh2 = j ? pk2(hH[2], hH[2]) : pk2(hL[2], hL[2]);
                    ull dh3 = j ? pk2(hH[3], hH[3]) : pk2(hL[3], hL[3]);
                    ull dx0 = pk2(x0, x0), dx1 = pk2(x1, x1);

                    ull c0 = ffma2(wh0[0][0], dh0, b0[0]);
                    ull c1 = ffma2(wh0[1][0], dh0, b0[1]);
                    c0 = ffma2(wh0[0][1], dh1, c0);  c1 = ffma2(wh0[1][1], dh1, c1);
                    c0 = ffma2(wh0[0][2], dh2, c0);  c1 = ffma2(wh0[1][2], dh2, c1);
                    c0 = ffma2(wh0[0][3], dh3, c0);  c1 = ffma2(wh0[1][3], dh3, c1);
                    c0 = ffma2(wi0[0][0], dx0, c0);  c1 = ffma2(wi0[1][0], dx0, c1);
                    c0 = ffma2(wi0[0][1], dx1, c0);  c1 = ffma2(wi0[1][1], dx1, c1);
                    a0[e] = c0; a1[e] = c1;
                }
            }
            // layer0 activations (paired) + packed shfl broadcast
            u32 h20[2];
            h20[0] = act_pair(a0[0], a0[1], a1[0], a1[1], c20[0]);
            h20[1] = act_pair(a0[2], a0[3], a1[2], a1[3], c20[1]);
#pragma unroll
            for (int P = 0; P < 2; P++) {
#pragma unroll
                for (int k = 0; k < 4; k++)
                    hb0[P][k] = __shfl_sync(0xFFFFFFFFu, h20[P], base + k);
            }

            // ================= layer 1: recurrent terms first ===============
#pragma unroll
            for (int P = 0; P < 2; P++) {
                float rL[4], rH[4], eL[4], eH[4];
#pragma unroll
                for (int k = 0; k < 4; k++) h2unpack(hb1[P][k], rL[k], rH[k]);
#pragma unroll
                for (int k = 0; k < 4; k++) h2unpack(hb0[P][k], eL[k], eH[k]);
#pragma unroll
                for (int j = 0; j < 2; j++) {
                    int e = 2 * P + j;
                    ull dr0 = j ? pk2(rH[0], rH[0]) : pk2(rL[0], rL[0]);
                    ull dr1 = j ? pk2(rH[1], rH[1]) : pk2(rL[1], rL[1]);
                    ull dr2 = j ? pk2(rH[2], rH[2]) : pk2(rL[2], rL[2]);
                    ull dr3 = j ? pk2(rH[3], rH[3]) : pk2(rL[3], rL[3]);

                    ull m0 = ffma2(wh1[0][0], dr0, b1[0]);
                    ull m1 = ffma2(wh1[1][0], dr0, b1[1]);
                    m0 = ffma2(wh1[0][1], dr1, m0);  m1 = ffma2(wh1[1][1], dr1, m1);
                    m0 = ffma2(wh1[0][2], dr2, m0);  m1 = ffma2(wh1[1][2], dr2, m1);
                    m0 = ffma2(wh1[0][3], dr3, m0);  m1 = ffma2(wh1[1][3], dr3, m1);

                    ull de0 = j ? pk2(eH[0], eH[0]) : pk2(eL[0], eL[0]);
                    ull de1 = j ? pk2(eH[1], eH[1]) : pk2(eL[1], eL[1]);
                    ull de2 = j ? pk2(eH[2], eH[2]) : pk2(eL[2], eL[2]);
                    ull de3 = j ? pk2(eH[3], eH[3]) : pk2(eL[3], eL[3]);
                    m0 = ffma2(wi1[0][0], de0, m0);  m1 = ffma2(wi1[1][0], de0, m1);
                    m0 = ffma2(wi1[0][1], de1, m0);  m1 = ffma2(wi1[1][1], de1, m1);
                    m0 = ffma2(wi1[0][2], de2, m0);  m1 = ffma2(wi1[1][2], de2, m1);
                    m0 = ffma2(wi1[0][3], de3, m0);  m1 = ffma2(wi1[1][3], de3, m1);
                    a0[e] = m0; a1[e] = m1;
                }
            }
            // layer1 activations + readout + packed shfl
            u32 h21[2];
            h21[0] = act_pair(a0[0], a0[1], a1[0], a1[1], c21[0]);
            h21[1] = act_pair(a0[2], a0[3], a1[2], a1[3], c21[1]);
            float wcur = s ? wo2 : wo;
#pragma unroll
            for (int P = 0; P < 2; P++) {
                float he0, he1;
                h2unpack(h21[P], he0, he1);
                z[2 * P]     = fmaf(he0, wcur, z[2 * P]);
                z[2 * P + 1] = fmaf(he1, wcur, z[2 * P + 1]);
#pragma unroll
                for (int k = 0; k < 4; k++)
                    hb1[P][k] = __shfl_sync(0xFFFFFFFFu, h21[P], base + k);
            }
        }
    }

    // quad reduction of readouts; lane u==0 stores a coalesced float4
#pragma unroll
    for (int e = 0; e < NE; e++) {
        z[e] += __shfl_xor_sync(0xFFFFFFFFu, z[e], 1);
        z[e] += __shfl_xor_sync(0xFFFFFFFFu, z[e], 2);
    }
    if (u == 0) {
        float bo = __ldg(&bout[0]);
        float4 r;
        r.x = rcpf(1.0f + ex2f(-1.442695040888963f * (z[0] + bo)));
        r.y = rcpf(1.0f + ex2f(-1.442695040888963f * (z[1] + bo)));
        r.z = rcpf(1.0f + ex2f(-1.442695040888963f * (z[2] + bo)));
        r.w = rcpf(1.0f + ex2f(-1.442695040888963f * (z[3] + bo)));
        *reinterpret_cast<float4*>(out + eA) = r;
    }
}

// ---------------------------------------------------------------------------
extern "C" void kernel_launch(void* const* d_in, const int* in_sizes, int n_in,
                              void* d_out, int out_size)
{
    const float* x    = (const float*)d_in[0];
    const float* Wih0 = (const float*)d_in[1];
    const float* Whh0 = (const float*)d_in[2];
    const float* bih0 = (const float*)d_in[3];
    const float* bhh0 = (const float*)d_in[4];
    const float* Wih1 = (const float*)d_in[5];
    const float* Whh1 = (const float*)d_in[6];
    const float* bih1 = (const float*)d_in[7];
    const float* bhh1 = (const float*)d_in[8];
    const float* Wout = (const float*)d_in[9];
    const float* bout = (const float*)d_in[10];

    int B = in_sizes[0] / (T_STEPS * 2);
    int threads = B;                   // 4 lanes per 4 elements
    int grid = (threads + 127) / 128;

    lstm_fused4p<<<grid, 128>>>(x, Wih0, Whh0, bih0, bhh0,
                                Wih1, Whh1, bih1, bhh1,
                                Wout, bout, (float*)d_out, B);
}

// round 8
// speedup vs baseline: 1.2662x; 1.2662x over previous
#include <cuda_runtime.h>

// ---------------------------------------------------------------------------
// R8: Fused 2-layer LSTM (H=4, I=2, T=50) + readout; 4 elements/thread as
//     2 element-PAIRS packed in f16x2 end-to-end.
// R4-R7 invariant ~212us regardless of occ/ILP/MUFU/shfl -> the wall is the
// fma-pipe MAC+packing stream: fma.rn.f32x2 has RF-banking rt=3 (3x64b
// operands) plus ~14 dup-MOVs/elem-step. Fix: MACs in HFMA2 (fma.rn.f16x2),
// rt=2, 32-bit operands, 2 MACs/instr, and the h operands arrive ALREADY
// PACKED as f16x2 element-pairs from the activations/shfl -> zero packing.
// Weights pre-duplicated (w,w) f16x2 in prologue (shared by all 4 elements).
// c-state update stays f32x2; readout and final sigmoid stay f32.
// ---------------------------------------------------------------------------

#define T_STEPS 50
typedef unsigned long long ull;
typedef unsigned int u32;

__device__ __forceinline__ ull pk2(float lo, float hi) {
    ull r; asm("mov.b64 %0, {%1, %2};" : "=l"(r) : "f"(lo), "f"(hi)); return r;
}
__device__ __forceinline__ void upk2(ull v, float& lo, float& hi) {
    asm("mov.b64 {%0, %1}, %2;" : "=f"(lo), "=f"(hi) : "l"(v));
}
__device__ __forceinline__ ull ffma2(ull a, ull b, ull c) {
    ull d; asm("fma.rn.f32x2 %0, %1, %2, %3;" : "=l"(d) : "l"(a), "l"(b), "l"(c));
    return d;
}
__device__ __forceinline__ ull mul2(ull a, ull b) {
    ull d; asm("mul.rn.f32x2 %0, %1, %2;" : "=l"(d) : "l"(a), "l"(b)); return d;
}
__device__ __forceinline__ float ex2f(float x) {
    float r; asm("ex2.approx.f32 %0, %1;" : "=f"(r) : "f"(x)); return r;
}
__device__ __forceinline__ float rcpf(float x) {
    float r; asm("rcp.approx.f32 %0, %1;" : "=f"(r) : "f"(x)); return r;
}

// ---- f16x2 helpers: lo half = even element, hi half = odd element ----------
__device__ __forceinline__ u32 h2pack(float lo, float hi) {
    u32 p; asm("cvt.rn.f16x2.f32 %0, %1, %2;" : "=r"(p) : "f"(hi), "f"(lo));
    return p;
}
__device__ __forceinline__ u32 h2dup(float w) {      // (w, w)
    u32 p; asm("cvt.rn.f16x2.f32 %0, %1, %1;" : "=r"(p) : "f"(w));
    return p;
}
__device__ __forceinline__ void h2unpack(u32 p, float& lo, float& hi) {
    asm("{\n\t.reg .b16 l, h;\n\tmov.b32 {l, h}, %2;\n\t"
        "cvt.f32.f16 %0, l;\n\tcvt.f32.f16 %1, h;\n\t}"
        : "=f"(lo), "=f"(hi) : "r"(p));
}
__device__ __forceinline__ u32 hfma2(u32 a, u32 b, u32 c) {
    u32 d; asm("fma.rn.f16x2 %0, %1, %2, %3;" : "=r"(d) : "r"(a), "r"(b), "r"(c));
    return d;
}
__device__ __forceinline__ u32 hmul2(u32 a, u32 b) {
    u32 d; asm("mul.rn.f16x2 %0, %1, %2;" : "=r"(d) : "r"(a), "r"(b)); return d;
}
__device__ __forceinline__ u32 h2tanh(u32 p) {
    u32 r; asm("tanh.approx.f16x2 %0, %1;" : "=r"(r) : "r"(p)); return r;
}
// sigmoid of prescaled pre-act (x0.5 folded into weights): 0.5*tanh(y)+0.5
__device__ __forceinline__ u32 h2sig(u32 p) {
    u32 r;
    asm("{\n\ttanh.approx.f16x2 %0, %1;\n\t"
        "fma.rn.f16x2 %0, %0, %2, %2;\n\t}"
        : "=r"(r) : "r"(p), "r"(0x38003800u));
    return r;
}
// f16x2 -> f32x2
__device__ __forceinline__ ull h2w(u32 p) {
    float lo, hi; h2unpack(p, lo, hi); return pk2(lo, hi);
}

// Pointwise LSTM block for one element-pair. Gate pre-acts yi/yf/yg/yo are
// f16x2 (2 elements); c2 is packed f32x2 cell state. Returns f16x2 h pair.
__device__ __forceinline__ u32 act_pair(u32 yi, u32 yf, u32 yg, u32 yo, ull& c2)
{
    u32 si = h2sig(yi);
    u32 sf = h2sig(yf);
    u32 so = h2sig(yo);
    u32 tg = h2tanh(yg);
    c2 = ffma2(h2w(sf), c2, mul2(h2w(si), h2w(tg)));
    float cl, ch; upk2(c2, cl, ch);
    u32 tc = h2tanh(h2pack(cl, ch));
    return hmul2(so, tc);
}

#define NE 4  // elements per thread = 2 pairs

__global__ __launch_bounds__(128, 4) void lstm_fused_h2(
    const float* __restrict__ x,     // [B, T, 2]
    const float* __restrict__ Wih0,  // [16, 2]
    const float* __restrict__ Whh0,  // [16, 4]
    const float* __restrict__ bih0,
    const float* __restrict__ bhh0,
    const float* __restrict__ Wih1,  // [16, 4]
    const float* __restrict__ Whh1,  // [16, 4]
    const float* __restrict__ bih1,
    const float* __restrict__ bhh1,
    const float* __restrict__ Wout,  // [1, 200], col = t*4 + u
    const float* __restrict__ bout,
    float* __restrict__ out,
    int B)
{
    int g = blockIdx.x * 128 + threadIdx.x;
    int q = g >> 2;            // quad owns elements 4q .. 4q+3
    int u = g & 3;             // hidden unit owned by this lane
    int eA = NE * q;
    if (eA >= B) return;
    int base = (threadIdx.x & 31) & ~3;

    // Gate rows for unit u (PyTorch order): i=u, f=4+u, g=8+u, o=12+u.
    // Sigmoid gates (i,f,o) scaled by 0.5; g-gate by 1.
    const int   row[4] = { u, 4 + u, 8 + u, 12 + u };
    const float scl[4] = { 0.5f, 0.5f, 1.0f, 0.5f };

    // Duplicated f16x2 weights (shared across all 4 elements).
    u32 wi0h[4][2], wh0h[4][4], bh0[4];
    u32 wi1h[4][4], wh1h[4][4], bh1[4];
#pragma unroll
    for (int G = 0; G < 4; G++) {
        int r = row[G];
        float s = scl[G];
#pragma unroll
        for (int k = 0; k < 2; k++)
            wi0h[G][k] = h2dup(s * __ldg(&Wih0[r * 2 + k]));
#pragma unroll
        for (int k = 0; k < 4; k++) {
            wh0h[G][k] = h2dup(s * __ldg(&Whh0[r * 4 + k]));
            wi1h[G][k] = h2dup(s * __ldg(&Wih1[r * 4 + k]));
            wh1h[G][k] = h2dup(s * __ldg(&Whh1[r * 4 + k]));
        }
        bh0[G] = h2dup(s * (__ldg(&bih0[r]) + __ldg(&bhh0[r])));
        bh1[G] = h2dup(s * (__ldg(&bih1[r]) + __ldg(&bhh1[r])));
    }

    // State: f32x2 cell per pair per layer; f16x2 h broadcasts.
    ull c20[2] = {0ull, 0ull}, c21[2] = {0ull, 0ull};
    u32 hb0[2][4] = {{0u,0u,0u,0u},{0u,0u,0u,0u}};
    u32 hb1[2][4] = {{0u,0u,0u,0u},{0u,0u,0u,0u}};
    float z[NE] = {0.f, 0.f, 0.f, 0.f};

    const float4* xb = reinterpret_cast<const float4*>(x + (size_t)eA * (T_STEPS * 2));

#pragma unroll 1
    for (int tt = 0; tt < T_STEPS / 2; ++tt) {
        // Load 2 timesteps x 4 elements; immediately pack into f16x2 pairs:
        // xp[P][s][comp], P=pair, s=sub-step, comp=x0/x1.
        u32 xp[2][2][2];
#pragma unroll
        for (int P = 0; P < 2; P++) {
            float4 va = __ldg(&xb[tt + (2 * P) * (T_STEPS / 2)]);
            float4 vb = __ldg(&xb[tt + (2 * P + 1) * (T_STEPS / 2)]);
            xp[P][0][0] = h2pack(va.x, vb.x);
            xp[P][0][1] = h2pack(va.y, vb.y);
            xp[P][1][0] = h2pack(va.z, vb.z);
            xp[P][1][1] = h2pack(va.w, vb.w);
        }
        float wo  = __ldg(&Wout[(2 * tt) * 4 + u]);
        float wo2 = __ldg(&Wout[(2 * tt + 1) * 4 + u]);

#pragma unroll
        for (int s = 0; s < 2; s++) {
            u32 h20[2], h21[2];

            // ---- layer 0: x-terms first (ready early), h-terms after ----
#pragma unroll
            for (int P = 0; P < 2; P++) {
                u32 yi = hfma2(wi0h[0][0], xp[P][s][0], bh0[0]);
                u32 yf = hfma2(wi0h[1][0], xp[P][s][0], bh0[1]);
                u32 yg = hfma2(wi0h[2][0], xp[P][s][0], bh0[2]);
                u32 yo = hfma2(wi0h[3][0], xp[P][s][0], bh0[3]);
                yi = hfma2(wi0h[0][1], xp[P][s][1], yi);
                yf = hfma2(wi0h[1][1], xp[P][s][1], yf);
                yg = hfma2(wi0h[2][1], xp[P][s][1], yg);
                yo = hfma2(wi0h[3][1], xp[P][s][1], yo);
#pragma unroll
                for (int k = 0; k < 4; k++) {
                    yi = hfma2(wh0h[0][k], hb0[P][k], yi);
                    yf = hfma2(wh0h[1][k], hb0[P][k], yf);
                    yg = hfma2(wh0h[2][k], hb0[P][k], yg);
                    yo = hfma2(wh0h[3][k], hb0[P][k], yo);
                }
                h20[P] = act_pair(yi, yf, yg, yo, c20[P]);
            }
            // packed shfl broadcast of layer0 h
#pragma unroll
            for (int P = 0; P < 2; P++) {
#pragma unroll
                for (int k = 0; k < 4; k++)
                    hb0[P][k] = __shfl_sync(0xFFFFFFFFu, h20[P], base + k);
            }

            // ---- layer 1: recurrent (old hb1) first, fresh hb0 last ----
#pragma unroll
            for (int P = 0; P < 2; P++) {
                u32 yi = hfma2(wh1h[0][0], hb1[P][0], bh1[0]);
                u32 yf = hfma2(wh1h[1][0], hb1[P][0], bh1[1]);
                u32 yg = hfma2(wh1h[2][0], hb1[P][0], bh1[2]);
                u32 yo = hfma2(wh1h[3][0], hb1[P][0], bh1[3]);
#pragma unroll
                for (int k = 1; k < 4; k++) {
                    yi = hfma2(wh1h[0][k], hb1[P][k], yi);
                    yf = hfma2(wh1h[1][k], hb1[P][k], yf);
                    yg = hfma2(wh1h[2][k], hb1[P][k], yg);
                    yo = hfma2(wh1h[3][k], hb1[P][k], yo);
                }
#pragma unroll
                for (int k = 0; k < 4; k++) {
                    yi = hfma2(wi1h[0][k], hb0[P][k], yi);
                    yf = hfma2(wi1h[1][k], hb0[P][k], yf);
                    yg = hfma2(wi1h[2][k], hb0[P][k], yg);
                    yo = hfma2(wi1h[3][k], hb0[P][k], yo);
                }
                h21[P] = act_pair(yi, yf, yg, yo, c21[P]);
            }

            // readout (f32) + packed shfl broadcast of layer1 h
            float wcur = s ? wo2 : wo;
#pragma unroll
            for (int P = 0; P < 2; P++) {
                float he0, he1;
                h2unpack(h21[P], he0, he1);
                z[2 * P]     = fmaf(he0, wcur, z[2 * P]);
                z[2 * P + 1] = fmaf(he1, wcur, z[2 * P + 1]);
#pragma unroll
                for (int k = 0; k < 4; k++)
                    hb1[P][k] = __shfl_sync(0xFFFFFFFFu, h21[P], base + k);
            }
        }
    }

    // quad reduction of readouts; lane u==0 stores a coalesced float4
#pragma unroll
    for (int e = 0; e < NE; e++) {
        z[e] += __shfl_xor_sync(0xFFFFFFFFu, z[e], 1);
        z[e] += __shfl_xor_sync(0xFFFFFFFFu, z[e], 2);
    }
    if (u == 0) {
        float bo = __ldg(&bout[0]);
        float4 r;
        r.x = rcpf(1.0f + ex2f(-1.442695040888963f * (z[0] + bo)));
        r.y = rcpf(1.0f + ex2f(-1.442695040888963f * (z[1] + bo)));
        r.z = rcpf(1.0f + ex2f(-1.442695040888963f * (z[2] + bo)));
        r.w = rcpf(1.0f + ex2f(-1.442695040888963f * (z[3] + bo)));
        *reinterpret_cast<float4*>(out + eA) = r;
    }
}

// ---------------------------------------------------------------------------
extern "C" void kernel_launch(void* const* d_in, const int* in_sizes, int n_in,
                              void* d_out, int out_size)
{
    const float* x    = (const float*)d_in[0];
    const float* Wih0 = (const float*)d_in[1];
    const float* Whh0 = (const float*)d_in[2];
    const float* bih0 = (const float*)d_in[3];
    const float* bhh0 = (const float*)d_in[4];
    const float* Wih1 = (const float*)d_in[5];
    const float* Whh1 = (const float*)d_in[6];
    const float* bih1 = (const float*)d_in[7];
    const float* bhh1 = (const float*)d_in[8];
    const float* Wout = (const float*)d_in[9];
    const float* bout = (const float*)d_in[10];

    int B = in_sizes[0] / (T_STEPS * 2);
    int threads = B;                   // 4 lanes per 4 elements
    int grid = (threads + 127) / 128;

    lstm_fused_h2<<<grid, 128>>>(x, Wih0, Whh0, bih0, bhh0,
                                 Wih1, Whh1, bih1, bhh1,
                                 Wout, bout, (float*)d_out, B);
}

// round 9
// speedup vs baseline: 1.3854x; 1.0942x over previous
#include <cuda_runtime.h>

// ---------------------------------------------------------------------------
// R9: Fused 2-layer LSTM (H=4, I=2, T=50) + readout; 4 elements/thread as
//     2 element-PAIRS packed in f16x2 END-TO-END — now including the CELL
//     STATE. R8 (HFMA2 MACs, f16x2 h) won 203->175us with fma=62%; remaining
//     fat was act_pair's f16<->f32 conversions (3 h2w + pack/unpack per pair
//     per layer-step, ~15 ops) sitting on the h-recurrence critical path.
//     Cell update is now pure f16x2: c = hfma2(sf, c, hmul2(si, tg));
//     tc = tanh.approx.f16x2(c). act_pair = 5 MUFU + 6 HFMA2, zero cvts.
// Weights pre-duplicated (w,w) f16x2 (shared by all 4 elements); readout and
// final sigmoid stay f32.
// ---------------------------------------------------------------------------

#define T_STEPS 50
typedef unsigned int u32;

__device__ __forceinline__ float ex2f(float x) {
    float r; asm("ex2.approx.f32 %0, %1;" : "=f"(r) : "f"(x)); return r;
}
__device__ __forceinline__ float rcpf(float x) {
    float r; asm("rcp.approx.f32 %0, %1;" : "=f"(r) : "f"(x)); return r;
}

// ---- f16x2 helpers: lo half = even element, hi half = odd element ----------
__device__ __forceinline__ u32 h2pack(float lo, float hi) {
    u32 p; asm("cvt.rn.f16x2.f32 %0, %1, %2;" : "=r"(p) : "f"(hi), "f"(lo));
    return p;
}
__device__ __forceinline__ u32 h2dup(float w) {      // (w, w)
    u32 p; asm("cvt.rn.f16x2.f32 %0, %1, %1;" : "=r"(p) : "f"(w));
    return p;
}
__device__ __forceinline__ void h2unpack(u32 p, float& lo, float& hi) {
    asm("{\n\t.reg .b16 l, h;\n\tmov.b32 {l, h}, %2;\n\t"
        "cvt.f32.f16 %0, l;\n\tcvt.f32.f16 %1, h;\n\t}"
        : "=f"(lo), "=f"(hi) : "r"(p));
}
__device__ __forceinline__ u32 hfma2(u32 a, u32 b, u32 c) {
    u32 d; asm("fma.rn.f16x2 %0, %1, %2, %3;" : "=r"(d) : "r"(a), "r"(b), "r"(c));
    return d;
}
__device__ __forceinline__ u32 hmul2(u32 a, u32 b) {
    u32 d; asm("mul.rn.f16x2 %0, %1, %2;" : "=r"(d) : "r"(a), "r"(b)); return d;
}
__device__ __forceinline__ u32 h2tanh(u32 p) {
    u32 r; asm("tanh.approx.f16x2 %0, %1;" : "=r"(r) : "r"(p)); return r;
}
// sigmoid of prescaled pre-act (x0.5 folded into weights): 0.5*tanh(y)+0.5
__device__ __forceinline__ u32 h2sig(u32 p) {
    u32 r;
    asm("{\n\ttanh.approx.f16x2 %0, %1;\n\t"
        "fma.rn.f16x2 %0, %0, %2, %2;\n\t}"
        : "=r"(r) : "r"(p), "r"(0x38003800u));
    return r;
}

// Pointwise LSTM block for one element-pair, all f16x2. c2 is f16x2 cell.
__device__ __forceinline__ u32 act_pair(u32 yi, u32 yf, u32 yg, u32 yo, u32& c2)
{
    u32 si = h2sig(yi);
    u32 sf = h2sig(yf);
    u32 so = h2sig(yo);
    u32 tg = h2tanh(yg);
    c2 = hfma2(sf, c2, hmul2(si, tg));
    return hmul2(so, h2tanh(c2));
}

#define NE 4  // elements per thread = 2 pairs

__global__ __launch_bounds__(128, 4) void lstm_h2c(
    const float* __restrict__ x,     // [B, T, 2]
    const float* __restrict__ Wih0,  // [16, 2]
    const float* __restrict__ Whh0,  // [16, 4]
    const float* __restrict__ bih0,
    const float* __restrict__ bhh0,
    const float* __restrict__ Wih1,  // [16, 4]
    const float* __restrict__ Whh1,  // [16, 4]
    const float* __restrict__ bih1,
    const float* __restrict__ bhh1,
    const float* __restrict__ Wout,  // [1, 200], col = t*4 + u
    const float* __restrict__ bout,
    float* __restrict__ out,
    int B)
{
    int g = blockIdx.x * 128 + threadIdx.x;
    int q = g >> 2;            // quad owns elements 4q .. 4q+3
    int u = g & 3;             // hidden unit owned by this lane
    int eA = NE * q;
    if (eA >= B) return;
    int base = (threadIdx.x & 31) & ~3;

    // Gate rows for unit u (PyTorch order): i=u, f=4+u, g=8+u, o=12+u.
    // Sigmoid gates (i,f,o) scaled by 0.5; g-gate by 1.
    const int   row[4] = { u, 4 + u, 8 + u, 12 + u };
    const float scl[4] = { 0.5f, 0.5f, 1.0f, 0.5f };

    // Duplicated f16x2 weights (shared across all 4 elements).
    u32 wi0h[4][2], wh0h[4][4], bh0[4];
    u32 wi1h[4][4], wh1h[4][4], bh1[4];
#pragma unroll
    for (int G = 0; G < 4; G++) {
        int r = row[G];
        float s = scl[G];
#pragma unroll
        for (int k = 0; k < 2; k++)
            wi0h[G][k] = h2dup(s * __ldg(&Wih0[r * 2 + k]));
#pragma unroll
        for (int k = 0; k < 4; k++) {
            wh0h[G][k] = h2dup(s * __ldg(&Whh0[r * 4 + k]));
            wi1h[G][k] = h2dup(s * __ldg(&Wih1[r * 4 + k]));
            wh1h[G][k] = h2dup(s * __ldg(&Whh1[r * 4 + k]));
        }
        bh0[G] = h2dup(s * (__ldg(&bih0[r]) + __ldg(&bhh0[r])));
        bh1[G] = h2dup(s * (__ldg(&bih1[r]) + __ldg(&bhh1[r])));
    }

    // State: f16x2 cell per pair per layer; f16x2 h broadcasts.
    u32 c20[2] = {0u, 0u}, c21[2] = {0u, 0u};
    u32 hb0[2][4] = {{0u,0u,0u,0u},{0u,0u,0u,0u}};
    u32 hb1[2][4] = {{0u,0u,0u,0u},{0u,0u,0u,0u}};
    float z[NE] = {0.f, 0.f, 0.f, 0.f};

    const float4* xb = reinterpret_cast<const float4*>(x + (size_t)eA * (T_STEPS * 2));

#pragma unroll 1
    for (int tt = 0; tt < T_STEPS / 2; ++tt) {
        // Load 2 timesteps x 4 elements; pack into f16x2 element pairs:
        // xp[P][s][comp], P=pair, s=sub-step, comp=x0/x1.
        u32 xp[2][2][2];
#pragma unroll
        for (int P = 0; P < 2; P++) {
            float4 va = __ldg(&xb[tt + (2 * P) * (T_STEPS / 2)]);
            float4 vb = __ldg(&xb[tt + (2 * P + 1) * (T_STEPS / 2)]);
            xp[P][0][0] = h2pack(va.x, vb.x);
            xp[P][0][1] = h2pack(va.y, vb.y);
            xp[P][1][0] = h2pack(va.z, vb.z);
            xp[P][1][1] = h2pack(va.w, vb.w);
        }
        float wo  = __ldg(&Wout[(2 * tt) * 4 + u]);
        float wo2 = __ldg(&Wout[(2 * tt + 1) * 4 + u]);

#pragma unroll
        for (int s = 0; s < 2; s++) {
            u32 h20[2], h21[2];

            // ---- layer 0: x-terms first (ready early), h-terms after ----
#pragma unroll
            for (int P = 0; P < 2; P++) {
                u32 yi = hfma2(wi0h[0][0], xp[P][s][0], bh0[0]);
                u32 yf = hfma2(wi0h[1][0], xp[P][s][0], bh0[1]);
                u32 yg = hfma2(wi0h[2][0], xp[P][s][0], bh0[2]);
                u32 yo = hfma2(wi0h[3][0], xp[P][s][0], bh0[3]);
                yi = hfma2(wi0h[0][1], xp[P][s][1], yi);
                yf = hfma2(wi0h[1][1], xp[P][s][1], yf);
                yg = hfma2(wi0h[2][1], xp[P][s][1], yg);
                yo = hfma2(wi0h[3][1], xp[P][s][1], yo);
#pragma unroll
                for (int k = 0; k < 4; k++) {
                    yi = hfma2(wh0h[0][k], hb0[P][k], yi);
                    yf = hfma2(wh0h[1][k], hb0[P][k], yf);
                    yg = hfma2(wh0h[2][k], hb0[P][k], yg);
                    yo = hfma2(wh0h[3][k], hb0[P][k], yo);
                }
                h20[P] = act_pair(yi, yf, yg, yo, c20[P]);
            }
            // packed shfl broadcast of layer0 h
#pragma unroll
            for (int P = 0; P < 2; P++) {
#pragma unroll
                for (int k = 0; k < 4; k++)
                    hb0[P][k] = __shfl_sync(0xFFFFFFFFu, h20[P], base + k);
            }

            // ---- layer 1: recurrent (old hb1) first, fresh hb0 last ----
#pragma unroll
            for (int P = 0; P < 2; P++) {
                u32 yi = hfma2(wh1h[0][0], hb1[P][0], bh1[0]);
                u32 yf = hfma2(wh1h[1][0], hb1[P][0], bh1[1]);
                u32 yg = hfma2(wh1h[2][0], hb1[P][0], bh1[2]);
                u32 yo = hfma2(wh1h[3][0], hb1[P][0], bh1[3]);
#pragma unroll
                for (int k = 1; k < 4; k++) {
                    yi = hfma2(wh1h[0][k], hb1[P][k], yi);
                    yf = hfma2(wh1h[1][k], hb1[P][k], yf);
                    yg = hfma2(wh1h[2][k], hb1[P][k], yg);
                    yo = hfma2(wh1h[3][k], hb1[P][k], yo);
                }
#pragma unroll
                for (int k = 0; k < 4; k++) {
                    yi = hfma2(wi1h[0][k], hb0[P][k], yi);
                    yf = hfma2(wi1h[1][k], hb0[P][k], yf);
                    yg = hfma2(wi1h[2][k], hb0[P][k], yg);
                    yo = hfma2(wi1h[3][k], hb0[P][k], yo);
                }
                h21[P] = act_pair(yi, yf, yg, yo, c21[P]);
            }

            // readout (f32) + packed shfl broadcast of layer1 h
            float wcur = s ? wo2 : wo;
#pragma unroll
            for (int P = 0; P < 2; P++) {
                float he0, he1;
                h2unpack(h21[P], he0, he1);
                z[2 * P]     = fmaf(he0, wcur, z[2 * P]);
                z[2 * P + 1] = fmaf(he1, wcur, z[2 * P + 1]);
#pragma unroll
                for (int k = 0; k < 4; k++)
                    hb1[P][k] = __shfl_sync(0xFFFFFFFFu, h21[P], base + k);
            }
        }
    }

    // quad reduction of readouts; lane u==0 stores a coalesced float4
#pragma unroll
    for (int e = 0; e < NE; e++) {
        z[e] += __shfl_xor_sync(0xFFFFFFFFu, z[e], 1);
        z[e] += __shfl_xor_sync(0xFFFFFFFFu, z[e], 2);
    }
    if (u == 0) {
        float bo = __ldg(&bout[0]);
        float4 r;
        r.x = rcpf(1.0f + ex2f(-1.442695040888963f * (z[0] + bo)));
        r.y = rcpf(1.0f + ex2f(-1.442695040888963f * (z[1] + bo)));
        r.z = rcpf(1.0f + ex2f(-1.442695040888963f * (z[2] + bo)));
        r.w = rcpf(1.0f + ex2f(-1.442695040888963f * (z[3] + bo)));
        *reinterpret_cast<float4*>(out + eA) = r;
    }
}

// ---------------------------------------------------------------------------
extern "C" void kernel_launch(void* const* d_in, const int* in_sizes, int n_in,
                              void* d_out, int out_size)
{
    const float* x    = (const float*)d_in[0];
    const float* Wih0 = (const float*)d_in[1];
    const float* Whh0 = (const float*)d_in[2];
    const float* bih0 = (const float*)d_in[3];
    const float* bhh0 = (const float*)d_in[4];
    const float* Wih1 = (const float*)d_in[5];
    const float* Whh1 = (const float*)d_in[6];
    const float* bih1 = (const float*)d_in[7];
    const float* bhh1 = (const float*)d_in[8];
    const float* Wout = (const float*)d_in[9];
    const float* bout = (const float*)d_in[10];

    int B = in_sizes[0] / (T_STEPS * 2);
    int threads = B;                   // 4 lanes per 4 elements
    int grid = (threads + 127) / 128;

    lstm_h2c<<<grid, 128>>>(x, Wih0, Whh0, bih0, bhh0,
                            Wih1, Whh1, bih1, bhh1,
                            Wout, bout, (float*)d_out, B);
}